// round 3
// baseline (speedup 1.0000x reference)
#include <cuda_runtime.h>
#include <math.h>

// Problem constants
#define BB   4
#define NN   30000
#define FFd  60000
#define NNZk 720000

static const size_t SZ_V = (size_t)BB * NN * 128;   // 15,360,000
static const size_t SZ_F = (size_t)BB * FFd * 128;  // 30,720,000

// ---------------- scratch (static device arrays; referenced directly by kernels) -----
__device__ float  g_xin[15360000];   // elu(v)
__device__ float  g_fin[30720000];   // elu(f)
__device__ float  g_t0 [30720000];   // spbmm1 out  [B,F,128]
__device__ float  g_g  [30720000];   // elu(f_out)
__device__ float  g_t1 [15360000];   // spbmm2 out  [B,N,128]
__device__ double g_stats0[512];     // [0:256) sum, [256:512) sumsq
__device__ double g_stats1[512];
__device__ float  g_w0p[32768];      // BN-folded fc0 weight [128][256]
__device__ float  g_b0p[128];
__device__ float  g_w1p[32768];
__device__ float  g_b1p[128];

// ---------------- elementwise ----------------
__device__ __forceinline__ float elu1(float x) { return x > 0.f ? x : expm1f(x); }

// WHICH==0: out = g_xin (n4 = SZ_V/4); WHICH==1: out = g_fin
template <int WHICH>
__global__ void elu4_kernel(const float4* __restrict__ in, int n4) {
    int i = blockIdx.x * blockDim.x + threadIdx.x;
    if (i >= n4) return;
    float4 v = in[i];
    v.x = elu1(v.x); v.y = elu1(v.y); v.z = elu1(v.z); v.w = elu1(v.w);
    float4* out = (float4*)(WHICH == 0 ? g_xin : g_fin);
    out[i] = v;
}

// WHICH: 0 -> zero g_t0 (nf4), 1 -> zero g_t1 (nv4), 2 -> zero g_stats0, 3 -> zero g_stats1
template <int WHICH>
__global__ void zero4_kernel(int n4) {
    int i = blockIdx.x * blockDim.x + threadIdx.x;
    if (i >= n4) return;
    float4* p = (WHICH == 0) ? (float4*)g_t0
              : (WHICH == 1) ? (float4*)g_t1
              : (WHICH == 2) ? (float4*)g_stats0
                             : (float4*)g_stats1;
    p[i] = make_float4(0.f, 0.f, 0.f, 0.f);
}

// ---------------- sparse COO spmm: dst[b, rows[e], :] += vals[e] * src[b, cols[e], :] --
// Channel tensors viewed flat: index (b, i4, c32) -> b*stride + i4*32 + c32.
// PASS==0: src=g_xin (stride NN*128),  dst=g_t0 (stride FFd*128)
// PASS==1: src=g_g   (stride FFd*128), dst=g_t1 (stride NN*128)
template <int PASS>
__global__ void spbmm_kernel(const int* __restrict__ rows, const int* __restrict__ cols,
                             const float* __restrict__ vals, int nnz) {
    int w    = (blockIdx.x * blockDim.x + threadIdx.x) >> 5;
    int lane = threadIdx.x & 31;
    if (w >= nnz) return;
    int   r = rows[w];
    int   c = cols[w];
    float v = vals[w];
    const size_t srcStride = (PASS == 0) ? (size_t)NN * 128 : (size_t)FFd * 128;
    const size_t dstStride = (PASS == 0) ? (size_t)FFd * 128 : (size_t)NN * 128;
    const float* s = (PASS == 0 ? g_xin : g_g) + (size_t)c * 32 + lane;
    float*       d = (PASS == 0 ? g_t0  : g_t1) + (size_t)r * 32 + lane;
#pragma unroll
    for (int b = 0; b < 4; b++) {
        atomicAdd(d + b * dstStride, v * s[b * srcStride]);
    }
}

// ---------------- BN column statistics over concat([A0, A1]) viewed as [M, 256] -------
// PASS==0: A0=g_fin, A1=g_t0, stats=g_stats0;  PASS==1: A0=g_xin, A1=g_t1, stats=g_stats1
template <int PASS>
__global__ void stats_kernel(int M) {
    int j = threadIdx.x;  // 0..255 = column
    const float* A0 = (PASS == 0) ? g_fin : g_xin;
    const float* A1 = (PASS == 0) ? g_t0  : g_t1;
    double* stats   = (PASS == 0) ? g_stats0 : g_stats1;
    const float* src = (j < 128) ? (A0 + j) : (A1 + (j - 128));
    double s = 0.0, s2 = 0.0;
    for (int r = blockIdx.x; r < M; r += gridDim.x) {
        float x = src[(size_t)r * 128];
        s  += (double)x;
        s2 += (double)x * (double)x;
    }
    atomicAdd(&stats[j], s);
    atomicAdd(&stats[256 + j], s2);
}

// ---- finalize BN + fold into linear: wp[o][j] = w[o][j]*a[j]; bp[o] = b[o] + sum_j sh[j]*w[o][j]
template <int PASS>
__global__ void finalize_fold_kernel(const float* __restrict__ gamma, const float* __restrict__ beta,
                                     const float* __restrict__ w, const float* __restrict__ bias,
                                     int M) {
    __shared__ float a_s[256], sh_s[256];
    const double* stats = (PASS == 0) ? g_stats0 : g_stats1;
    float* wp = (PASS == 0) ? g_w0p : g_w1p;
    float* bp = (PASS == 0) ? g_b0p : g_b1p;
    int j = threadIdx.x;
    double invM = 1.0 / (double)M;
    double mu   = stats[j] * invM;
    double var  = stats[256 + j] * invM - mu * mu;
    float a  = gamma[j] * rsqrtf((float)var + 1e-5f);
    float sh = beta[j] - (float)mu * a;
    a_s[j] = a; sh_s[j] = sh;
    __syncthreads();
    for (int idx = j; idx < 128 * 256; idx += 256) {
        int jj = idx & 255;
        wp[idx] = w[idx] * a_s[jj];
    }
    if (j < 128) {
        float s = bias[j];
        const float* wr = w + j * 256;
        for (int q = 0; q < 256; q++) s += sh_s[q] * wr[q];
        bp[j] = s;
    }
}

// ---------------- SGEMM: out[M,128] = [A0|A1][M,256] @ Wp[128,256]^T + bp --------------
// PASS==0: A0=g_fin, A1=g_t0, Wp=g_w0p, bp=g_b0p, out=out_f, elu-copy -> g_g
// PASS==1: A0=g_xin, A1=g_t1, Wp=g_w1p, bp=g_b1p, out=out_v, resid=v_in
template <int PASS>
__global__ void __launch_bounds__(256, 2)
gemm_kernel(const float* __restrict__ resid, float* __restrict__ out, int M) {
    const float* A0 = (PASS == 0) ? g_fin : g_xin;
    const float* A1 = (PASS == 0) ? g_t0  : g_t1;
    const float* Wp = (PASS == 0) ? g_w0p : g_w1p;
    const float* bp = (PASS == 0) ? g_b0p : g_b1p;

    __shared__ float As[16][128];
    __shared__ float Bs[16][128];
    int tid = threadIdx.x;       // 0..255
    int tx  = tid & 15;          // n-tile 0..15
    int ty  = tid >> 4;          // m-tile 0..15
    int m0  = blockIdx.x * 128;

    float acc[8][8];
#pragma unroll
    for (int y = 0; y < 8; y++)
#pragma unroll
        for (int x = 0; x < 8; x++) acc[y][x] = 0.f;

    for (int t = 0; t < 16; t++) {
        const float* Asrc = (t < 8) ? A0 : A1;
        int kbase = (t & 7) * 16;
        // A tile 128x16 (512 float4, 2 per thread), stored transposed As[k][m]
#pragma unroll
        for (int i = 0; i < 2; i++) {
            int idx = tid * 2 + i;        // 0..511
            int row = idx >> 2;           // 0..127
            int c4  = idx & 3;            // 0..3
            int m   = m0 + row;
            float4 va = (m < M) ? *(const float4*)(Asrc + (size_t)m * 128 + kbase + c4 * 4)
                                : make_float4(0.f, 0.f, 0.f, 0.f);
            As[c4 * 4 + 0][row] = va.x;
            As[c4 * 4 + 1][row] = va.y;
            As[c4 * 4 + 2][row] = va.z;
            As[c4 * 4 + 3][row] = va.w;
        }
        // B tile: Wp[n][t*16 + k] -> Bs[k][n]
#pragma unroll
        for (int i = 0; i < 2; i++) {
            int idx = tid * 2 + i;
            int n   = idx >> 2;
            int c4  = idx & 3;
            float4 vb = *(const float4*)(Wp + n * 256 + t * 16 + c4 * 4);
            Bs[c4 * 4 + 0][n] = vb.x;
            Bs[c4 * 4 + 1][n] = vb.y;
            Bs[c4 * 4 + 2][n] = vb.z;
            Bs[c4 * 4 + 3][n] = vb.w;
        }
        __syncthreads();
#pragma unroll
        for (int k = 0; k < 16; k++) {
            float af[8], bf[8];
#pragma unroll
            for (int q = 0; q < 8; q++) af[q] = As[k][ty * 8 + q];
#pragma unroll
            for (int q = 0; q < 8; q++) bf[q] = Bs[k][tx * 8 + q];
#pragma unroll
            for (int y = 0; y < 8; y++)
#pragma unroll
                for (int x = 0; x < 8; x++) acc[y][x] += af[y] * bf[x];
        }
        __syncthreads();
    }

    // epilogue
    float bv[8];
#pragma unroll
    for (int x = 0; x < 8; x++) bv[x] = bp[tx * 8 + x];

#pragma unroll
    for (int y = 0; y < 8; y++) {
        int m = m0 + ty * 8 + y;
        if (m >= M) break;
        size_t base = (size_t)m * 128 + tx * 8;
        float vo[8];
#pragma unroll
        for (int x = 0; x < 8; x++) vo[x] = acc[y][x] + bv[x];
        if (PASS == 1) {
            float4 r0 = *(const float4*)(resid + base);
            float4 r1 = *(const float4*)(resid + base + 4);
            vo[0] += r0.x; vo[1] += r0.y; vo[2] += r0.z; vo[3] += r0.w;
            vo[4] += r1.x; vo[5] += r1.y; vo[6] += r1.z; vo[7] += r1.w;
        }
        *(float4*)(out + base)     = make_float4(vo[0], vo[1], vo[2], vo[3]);
        *(float4*)(out + base + 4) = make_float4(vo[4], vo[5], vo[6], vo[7]);
        if (PASS == 0) {
            float e[8];
#pragma unroll
            for (int x = 0; x < 8; x++) e[x] = elu1(vo[x]);
            *(float4*)(g_g + base)     = make_float4(e[0], e[1], e[2], e[3]);
            *(float4*)(g_g + base + 4) = make_float4(e[4], e[5], e[6], e[7]);
        }
    }
}

// ---------------- launch ----------------
extern "C" void kernel_launch(void* const* d_in, const int* in_sizes, int n_in,
                              void* d_out, int out_size) {
    const int*   Di_rows  = (const int*)d_in[0];
    const int*   Di_cols  = (const int*)d_in[1];
    const float* Di_vals  = (const float*)d_in[2];
    const int*   DiA_rows = (const int*)d_in[3];
    const int*   DiA_cols = (const int*)d_in[4];
    const float* DiA_vals = (const float*)d_in[5];
    const float* v_in     = (const float*)d_in[6];
    const float* f_in     = (const float*)d_in[7];
    const float* bn0_g    = (const float*)d_in[8];
    const float* bn0_b    = (const float*)d_in[9];
    const float* fc0_w    = (const float*)d_in[10];
    const float* fc0_b    = (const float*)d_in[11];
    const float* bn1_g    = (const float*)d_in[12];
    const float* bn1_b    = (const float*)d_in[13];
    const float* fc1_w    = (const float*)d_in[14];
    const float* fc1_b    = (const float*)d_in[15];

    float* out_v = (float*)d_out;                 // v + v_out : [4,30000,128]
    float* out_f = out_v + SZ_V;                  // f_out     : [4,60000,128]

    const int T = 256;
    const int nv4 = (int)(SZ_V / 4);   // 3,840,000
    const int nf4 = (int)(SZ_F / 4);   // 7,680,000

    // 1) elu inputs
    elu4_kernel<0><<<(nv4 + T - 1) / T, T>>>((const float4*)v_in, nv4);
    elu4_kernel<1><<<(nf4 + T - 1) / T, T>>>((const float4*)f_in, nf4);

    // 2) spbmm1: g_t0 = Di @ g_xin
    zero4_kernel<0><<<(nf4 + T - 1) / T, T>>>(nf4);
    spbmm_kernel<0><<<(NNZk * 32 + T - 1) / T, T>>>(Di_rows, Di_cols, Di_vals, NNZk);

    // 3) BN0 stats + fold into fc0
    zero4_kernel<2><<<1, T>>>(256);   // 512 doubles = 256 float4
    stats_kernel<0><<<4096, 256>>>(BB * FFd);
    finalize_fold_kernel<0><<<1, 256>>>(bn0_g, bn0_b, fc0_w, fc0_b, BB * FFd);

    // 4) gemm0: f_out (+ elu copy into g_g)
    gemm_kernel<0><<<(BB * FFd + 127) / 128, 256>>>(nullptr, out_f, BB * FFd);

    // 5) spbmm2: g_t1 = DiA @ g_g
    zero4_kernel<1><<<(nv4 + T - 1) / T, T>>>(nv4);
    spbmm_kernel<1><<<(NNZk * 32 + T - 1) / T, T>>>(DiA_rows, DiA_cols, DiA_vals, NNZk);

    // 6) BN1 stats + fold into fc1
    zero4_kernel<3><<<1, T>>>(256);
    stats_kernel<1><<<4096, 256>>>(BB * NN);
    finalize_fold_kernel<1><<<1, 256>>>(bn1_g, bn1_b, fc1_w, fc1_b, BB * NN);

    // 7) gemm1: out_v = v + linear(...)
    gemm_kernel<1><<<(BB * NN + 127) / 128, 256>>>(v_in, out_v, BB * NN);
}

// round 7
// speedup vs baseline: 1.4978x; 1.4978x over previous
#include <cuda_runtime.h>
#include <cuda_bf16.h>
#include <math.h>
#include <stdint.h>

// Problem constants
#define BB   4
#define NN   30000
#define FFd  60000
#define NNZk 720000

static const size_t SZ_V = (size_t)BB * NN * 128;   // 15,360,000
static const size_t SZ_F = (size_t)BB * FFd * 128;  // 30,720,000

// ---------------- scratch (static device arrays) ----------------
__device__ float  g_xin[15360000];   // elu(v)
__device__ float  g_fin[30720000];   // elu(f)
__device__ float  g_t0 [30720000];   // spbmm1 out  [B,F,128]
__device__ float  g_g  [30720000];   // elu(f_out)
__device__ float  g_t1 [15360000];   // spbmm2 out  [B,N,128]
__device__ double g_stats0[512];     // [0:256) sum, [256:512) sumsq
__device__ double g_stats1[512];
__device__ __nv_bfloat16 g_w0hi[32768], g_w0lo[32768];  // BN-folded fc0 weight, bf16 hi/lo [128][256]
__device__ __nv_bfloat16 g_w1hi[32768], g_w1lo[32768];
__device__ float  g_b0p[128];
__device__ float  g_b1p[128];

// ---------------- helpers ----------------
__device__ __forceinline__ uint32_t smem_u32(const void* p) {
    uint32_t a;
    asm("{ .reg .u64 t; cvta.to.shared.u64 t, %1; cvt.u32.u64 %0, t; }" : "=r"(a) : "l"(p));
    return a;
}

#define SW128(o) ((o) ^ (((o) >> 3) & 0x70))

__device__ __forceinline__ float elu1(float x) { return x > 0.f ? x : expm1f(x); }

__device__ __forceinline__ void ldsm4(uint32_t* d, uint32_t addr) {
    asm volatile("ldmatrix.sync.aligned.m8n8.x4.shared.b16 {%0,%1,%2,%3}, [%4];"
                 : "=r"(d[0]), "=r"(d[1]), "=r"(d[2]), "=r"(d[3]) : "r"(addr));
}

__device__ __forceinline__ void mma16816(float* c, const uint32_t* a, uint32_t b0, uint32_t b1) {
    asm volatile("mma.sync.aligned.m16n8k16.row.col.f32.bf16.bf16.f32 "
                 "{%0,%1,%2,%3}, {%4,%5,%6,%7}, {%8,%9}, {%0,%1,%2,%3};"
                 : "+f"(c[0]), "+f"(c[1]), "+f"(c[2]), "+f"(c[3])
                 : "r"(a[0]), "r"(a[1]), "r"(a[2]), "r"(a[3]), "r"(b0), "r"(b1));
}

// ---------------- elementwise ----------------
template <int WHICH>
__global__ void elu4_kernel(const float4* __restrict__ in, int n4) {
    int i = blockIdx.x * blockDim.x + threadIdx.x;
    if (i >= n4) return;
    float4 v = in[i];
    v.x = elu1(v.x); v.y = elu1(v.y); v.z = elu1(v.z); v.w = elu1(v.w);
    float4* out = (float4*)(WHICH == 0 ? g_xin : g_fin);
    out[i] = v;
}

template <int WHICH>
__global__ void zero4_kernel(int n4) {
    int i = blockIdx.x * blockDim.x + threadIdx.x;
    if (i >= n4) return;
    float4* p = (WHICH == 0) ? (float4*)g_t0
              : (WHICH == 1) ? (float4*)g_t1
              : (WHICH == 2) ? (float4*)g_stats0
                             : (float4*)g_stats1;
    p[i] = make_float4(0.f, 0.f, 0.f, 0.f);
}

// ---------------- sparse COO spmm (1 LDG.128 + 1 RED.v4 per lane) ----------------
template <int PASS>
__global__ void spbmm_kernel(const int* __restrict__ rows, const int* __restrict__ cols,
                             const float* __restrict__ vals, int nnz) {
    int w    = (blockIdx.x * blockDim.x + threadIdx.x) >> 5;
    int lane = threadIdx.x & 31;
    if (w >= nnz) return;
    int   r = rows[w];
    int   c = cols[w];
    float v = vals[w];
    int b = lane >> 3;
    int q = lane & 7;
    const size_t srcStride = (PASS == 0) ? (size_t)NN * 128 : (size_t)FFd * 128;
    const size_t dstStride = (PASS == 0) ? (size_t)FFd * 128 : (size_t)NN * 128;
    const float* sp = (PASS == 0 ? g_xin : g_g) + (size_t)b * srcStride + (size_t)c * 32 + q * 4;
    float*       dp = (PASS == 0 ? g_t0  : g_t1) + (size_t)b * dstStride + (size_t)r * 32 + q * 4;
    float4 x = *(const float4*)sp;
    x.x *= v; x.y *= v; x.z *= v; x.w *= v;
    asm volatile("red.global.add.v4.f32 [%0], {%1, %2, %3, %4};"
                 :: "l"(dp), "f"(x.x), "f"(x.y), "f"(x.z), "f"(x.w) : "memory");
}

// ---------------- BN column statistics over concat([A0, A1]) viewed as [M, 256] -------
template <int PASS>
__global__ void stats_kernel(int M) {
    int j = threadIdx.x;  // 0..255 = column
    const float* A0 = (PASS == 0) ? g_fin : g_xin;
    const float* A1 = (PASS == 0) ? g_t0  : g_t1;
    double* stats   = (PASS == 0) ? g_stats0 : g_stats1;
    const float* src = (j < 128) ? (A0 + j) : (A1 + (j - 128));
    double s = 0.0, s2 = 0.0;
    for (int r = blockIdx.x; r < M; r += gridDim.x) {
        float x = src[(size_t)r * 128];
        s  += (double)x;
        s2 += (double)x * (double)x;
    }
    atomicAdd(&stats[j], s);
    atomicAdd(&stats[256 + j], s2);
}

// ---- finalize BN + fold into linear; emit bf16 hi/lo weights + fused bias ----
template <int PASS>
__global__ void finalize_fold_kernel(const float* __restrict__ gamma, const float* __restrict__ beta,
                                     const float* __restrict__ w, const float* __restrict__ bias,
                                     int M) {
    __shared__ float a_s[256], sh_s[256];
    const double* stats = (PASS == 0) ? g_stats0 : g_stats1;
    __nv_bfloat16* whi = (PASS == 0) ? g_w0hi : g_w1hi;
    __nv_bfloat16* wlo = (PASS == 0) ? g_w0lo : g_w1lo;
    float* bp = (PASS == 0) ? g_b0p : g_b1p;
    int j = threadIdx.x;
    double invM = 1.0 / (double)M;
    double mu   = stats[j] * invM;
    double var  = stats[256 + j] * invM - mu * mu;
    float a  = gamma[j] * rsqrtf((float)var + 1e-5f);
    float sh = beta[j] - (float)mu * a;
    a_s[j] = a; sh_s[j] = sh;
    __syncthreads();
    for (int idx = j; idx < 128 * 256; idx += 256) {
        float wv = w[idx] * a_s[idx & 255];
        __nv_bfloat16 hi = __float2bfloat16(wv);
        __nv_bfloat16 lo = __float2bfloat16(wv - __bfloat162float(hi));
        whi[idx] = hi; wlo[idx] = lo;
    }
    if (j < 128) {
        float s = bias[j];
        const float* wr = w + j * 256;
        for (int q = 0; q < 256; q++) s += sh_s[q] * wr[q];
        bp[j] = s;
    }
}

// ---------------- HMMA bf16 GEMM: out[M,128] = [A0|A1][M,256] @ Wp[128,256]^T + bp ----
// 3-term compensation: D = Ahi*Whi + Ahi*Wlo + Alo*Whi.
// CTA tile 128x128, 8 warps = 4(M) x 2(N), each warp m32 x n64 via mma.m16n8k16.
// K chunked by 64 bf16 (= 128B SW128 rows in smem).
// PASS==0: A0=g_fin, A1=g_t0, W=g_w0*, bp=g_b0p, out=out_f, elu-copy -> g_g
// PASS==1: A0=g_xin, A1=g_t1, W=g_w1*, bp=g_b1p, out=out_v, resid=v_in

#define OF_BIAS 0                   // 128 floats
#define OF_AHI  1024                // 128 x 64 bf16 = 16384
#define OF_ALO  (1024 + 16384)
#define OF_WHI  (1024 + 32768)
#define OF_WLO  (1024 + 49152)
#define SMEM_SZ (1024 + 65536)      // 66560

template <int PASS>
__global__ void __launch_bounds__(256, 2)
gemm_mma_kernel(const float* __restrict__ resid, float* __restrict__ out, int M) {
    extern __shared__ char smem[];
    const float* A0 = (PASS == 0) ? g_fin : g_xin;
    const float* A1 = (PASS == 0) ? g_t0  : g_t1;
    const __nv_bfloat16* Whi = (PASS == 0) ? g_w0hi : g_w1hi;
    const __nv_bfloat16* Wlo = (PASS == 0) ? g_w0lo : g_w1lo;
    const float* bp = (PASS == 0) ? g_b0p : g_b1p;

    uint32_t sb = smem_u32(smem);
    int tid  = threadIdx.x;
    int wid  = tid >> 5;
    int lane = tid & 31;
    int m0   = blockIdx.x * 128;
    int wm   = (wid & 3) * 32;      // warp M offset in tile
    int wn   = (wid >> 2) * 64;     // warp N offset in tile

    if (tid < 128) *(float*)(smem + OF_BIAS + tid * 4) = bp[tid];

    float acc[2][8][4];
#pragma unroll
    for (int mt = 0; mt < 2; mt++)
#pragma unroll
        for (int nt = 0; nt < 8; nt++)
#pragma unroll
            for (int e = 0; e < 4; e++) acc[mt][nt][e] = 0.f;

    // ldmatrix per-lane source row/granule indices (lane -> 8x8 matrix row)
    int lrow = (lane & 7) + ((lane >> 3) & 1) * 8;  // 0..15
    int lkg  = lane >> 4;                           // 0..1 (k granule within k16)

    for (int ch = 0; ch < 4; ch++) {                // K chunks of 64
        const float* Asrc = (ch < 2) ? A0 : A1;
        int kbA = (ch & 1) * 64;
        int kgW = ch * 8;                           // W granule offset (64 bf16 = 8 x 16B)
        if (ch) __syncthreads();                    // protect previous chunk's reads

        // ---- stage A (convert f32 -> bf16 hi/lo) : 1024 granules, 4 per thread ----
#pragma unroll
        for (int i = 0; i < 4; i++) {
            int idx = tid + i * 256;
            int row = idx >> 3;
            int u   = idx & 7;
            float af[8];
            if (m0 + row < M) {
                const float* ap = Asrc + (size_t)(m0 + row) * 128 + kbA + u * 8;
                float4 a0 = *(const float4*)ap;
                float4 a1 = *(const float4*)(ap + 4);
                af[0]=a0.x; af[1]=a0.y; af[2]=a0.z; af[3]=a0.w;
                af[4]=a1.x; af[5]=a1.y; af[6]=a1.z; af[7]=a1.w;
            } else {
#pragma unroll
                for (int e = 0; e < 8; e++) af[e] = 0.f;
            }
            __nv_bfloat16 hi[8], lo[8];
#pragma unroll
            for (int e = 0; e < 8; e++) {
                hi[e] = __float2bfloat16(af[e]);
                lo[e] = __float2bfloat16(af[e] - __bfloat162float(hi[e]));
            }
            uint32_t off = SW128((uint32_t)(row * 128 + u * 16));
            *(uint4*)(smem + OF_AHI + off) = *(const uint4*)hi;
            *(uint4*)(smem + OF_ALO + off) = *(const uint4*)lo;
        }
        // ---- stage W (already bf16 hi/lo in global, [128][256] rows of 512B) ----
#pragma unroll
        for (int i = 0; i < 4; i++) {
            int idx = tid + i * 256;
            int row = idx >> 3;
            int u   = idx & 7;
            uint32_t off = SW128((uint32_t)(row * 128 + u * 16));
            *(uint4*)(smem + OF_WHI + off) = ((const uint4*)Whi)[row * 32 + kgW + u];
            *(uint4*)(smem + OF_WLO + off) = ((const uint4*)Wlo)[row * 32 + kgW + u];
        }
        __syncthreads();

        // ---- compute: 4 k16 steps ----
#pragma unroll
        for (int ks = 0; ks < 4; ks++) {
            uint32_t ahi[2][4], alo[2][4];
#pragma unroll
            for (int mt = 0; mt < 2; mt++) {
                uint32_t aoff = SW128((uint32_t)((wm + mt * 16 + lrow) * 128 + (ks * 2 + lkg) * 16));
                ldsm4(ahi[mt], sb + OF_AHI + aoff);
                ldsm4(alo[mt], sb + OF_ALO + aoff);
            }
#pragma unroll
            for (int nt2 = 0; nt2 < 4; nt2++) {
                uint32_t boff = SW128((uint32_t)((wn + nt2 * 16 + lrow) * 128 + (ks * 2 + lkg) * 16));
                uint32_t bh[4], bl[4];
                ldsm4(bh, sb + OF_WHI + boff);
                ldsm4(bl, sb + OF_WLO + boff);
                // x4 matrices: {t0.b0, t1.b0, t0.b1, t1.b1} -> tile0 regs (0,2), tile1 regs (1,3)
#pragma unroll
                for (int mt = 0; mt < 2; mt++) {
                    mma16816(acc[mt][nt2 * 2 + 0], ahi[mt], bh[0], bh[2]);
                    mma16816(acc[mt][nt2 * 2 + 1], ahi[mt], bh[1], bh[3]);
                    mma16816(acc[mt][nt2 * 2 + 0], ahi[mt], bl[0], bl[2]);
                    mma16816(acc[mt][nt2 * 2 + 1], ahi[mt], bl[1], bl[3]);
                    mma16816(acc[mt][nt2 * 2 + 0], alo[mt], bh[0], bh[2]);
                    mma16816(acc[mt][nt2 * 2 + 1], alo[mt], bh[1], bh[3]);
                }
            }
        }
    }

    // ---- epilogue ----
    const float* bias_s = (const float*)(smem + OF_BIAS);
    int r0 = lane >> 2;             // 0..7
    int cp = (lane & 3) * 2;        // 0,2,4,6
#pragma unroll
    for (int mt = 0; mt < 2; mt++) {
#pragma unroll
        for (int nt = 0; nt < 8; nt++) {
            int col = wn + nt * 8 + cp;
            float b0 = bias_s[col], b1 = bias_s[col + 1];
#pragma unroll
            for (int h = 0; h < 2; h++) {
                int rr = m0 + wm + mt * 16 + r0 + h * 8;
                if (rr >= M) continue;
                size_t base = (size_t)rr * 128 + col;
                float v0 = acc[mt][nt][h * 2 + 0] + b0;
                float v1 = acc[mt][nt][h * 2 + 1] + b1;
                if (PASS == 1) {
                    float2 rd = *(const float2*)(resid + base);
                    v0 += rd.x; v1 += rd.y;
                }
                *(float2*)(out + base) = make_float2(v0, v1);
                if (PASS == 0)
                    *(float2*)(g_g + base) = make_float2(elu1(v0), elu1(v1));
            }
        }
    }
}

// ---------------- launch ----------------
extern "C" void kernel_launch(void* const* d_in, const int* in_sizes, int n_in,
                              void* d_out, int out_size) {
    const int*   Di_rows  = (const int*)d_in[0];
    const int*   Di_cols  = (const int*)d_in[1];
    const float* Di_vals  = (const float*)d_in[2];
    const int*   DiA_rows = (const int*)d_in[3];
    const int*   DiA_cols = (const int*)d_in[4];
    const float* DiA_vals = (const float*)d_in[5];
    const float* v_in     = (const float*)d_in[6];
    const float* f_in     = (const float*)d_in[7];
    const float* bn0_g    = (const float*)d_in[8];
    const float* bn0_b    = (const float*)d_in[9];
    const float* fc0_w    = (const float*)d_in[10];
    const float* fc0_b    = (const float*)d_in[11];
    const float* bn1_g    = (const float*)d_in[12];
    const float* bn1_b    = (const float*)d_in[13];
    const float* fc1_w    = (const float*)d_in[14];
    const float* fc1_b    = (const float*)d_in[15];

    float* out_v = (float*)d_out;                 // v + v_out : [4,30000,128]
    float* out_f = out_v + SZ_V;                  // f_out     : [4,60000,128]

    const int T = 256;
    const int nv4 = (int)(SZ_V / 4);
    const int nf4 = (int)(SZ_F / 4);

    cudaFuncSetAttribute(gemm_mma_kernel<0>, cudaFuncAttributeMaxDynamicSharedMemorySize, SMEM_SZ);
    cudaFuncSetAttribute(gemm_mma_kernel<1>, cudaFuncAttributeMaxDynamicSharedMemorySize, SMEM_SZ);

    // 1) elu inputs
    elu4_kernel<0><<<(nv4 + T - 1) / T, T>>>((const float4*)v_in, nv4);
    elu4_kernel<1><<<(nf4 + T - 1) / T, T>>>((const float4*)f_in, nf4);

    // 2) spbmm1: g_t0 = Di @ g_xin
    zero4_kernel<0><<<(nf4 + T - 1) / T, T>>>(nf4);
    spbmm_kernel<0><<<(NNZk * 32 + T - 1) / T, T>>>(Di_rows, Di_cols, Di_vals, NNZk);

    // 3) BN0 stats + fold into fc0
    zero4_kernel<2><<<1, T>>>(256);
    stats_kernel<0><<<4096, 256>>>(BB * FFd);
    finalize_fold_kernel<0><<<1, 256>>>(bn0_g, bn0_b, fc0_w, fc0_b, BB * FFd);

    // 4) gemm0: f_out (+ elu copy into g_g)
    gemm_mma_kernel<0><<<(BB * FFd + 127) / 128, 256, SMEM_SZ>>>(nullptr, out_f, BB * FFd);

    // 5) spbmm2: g_t1 = DiA @ g_g
    zero4_kernel<1><<<(nv4 + T - 1) / T, T>>>(nv4);
    spbmm_kernel<1><<<(NNZk * 32 + T - 1) / T, T>>>(DiA_rows, DiA_cols, DiA_vals, NNZk);

    // 6) BN1 stats + fold into fc1
    zero4_kernel<3><<<1, T>>>(256);
    stats_kernel<1><<<4096, 256>>>(BB * NN);
    finalize_fold_kernel<1><<<1, 256>>>(bn1_g, bn1_b, fc1_w, fc1_b, BB * NN);

    // 7) gemm1: out_v = v + linear(...)
    gemm_mma_kernel<1><<<(BB * NN + 127) / 128, 256, SMEM_SZ>>>(v_in, out_v, BB * NN);
}

// round 8
// speedup vs baseline: 1.8364x; 1.2260x over previous
#include <cuda_runtime.h>
#include <cuda_bf16.h>
#include <math.h>
#include <stdint.h>

// Problem constants
#define BB   4
#define NN   30000
#define FFd  60000
#define NNZk 720000

static const size_t SZ_V = (size_t)BB * NN * 128;   // 15,360,000
static const size_t SZ_F = (size_t)BB * FFd * 128;  // 30,720,000

// ---------------- scratch (static device arrays) ----------------
__device__ float  g_xin[15360000];   // elu(v)
__device__ float  g_fin[30720000];   // elu(f)
__device__ float  g_t0 [30720000];   // spbmm1 out  [B,F,128]
__device__ float  g_g  [30720000];   // elu(f_out)
__device__ float  g_t1 [15360000];   // spbmm2 out  [B,N,128]
__device__ double g_stats0[512];     // [0:256) sum, [256:512) sumsq (concat cols)
__device__ double g_stats1[512];
__device__ __nv_bfloat16 g_w0hi[32768], g_w0lo[32768];  // BN-folded fc0 weight bf16 hi/lo [128][256]
__device__ __nv_bfloat16 g_w1hi[32768], g_w1lo[32768];
__device__ float  g_b0p[128];
__device__ float  g_b1p[128];

// ---------------- helpers ----------------
__device__ __forceinline__ uint32_t smem_u32(const void* p) {
    uint32_t a;
    asm("{ .reg .u64 t; cvta.to.shared.u64 t, %1; cvt.u32.u64 %0, t; }" : "=r"(a) : "l"(p));
    return a;
}

#define SW128(o) ((o) ^ (((o) >> 3) & 0x70))

__device__ __forceinline__ float elu1(float x) { return x > 0.f ? x : expm1f(x); }

__device__ __forceinline__ void ldsm4(uint32_t* d, uint32_t addr) {
    asm volatile("ldmatrix.sync.aligned.m8n8.x4.shared.b16 {%0,%1,%2,%3}, [%4];"
                 : "=r"(d[0]), "=r"(d[1]), "=r"(d[2]), "=r"(d[3]) : "r"(addr));
}

__device__ __forceinline__ void mma16816(float* c, const uint32_t* a, uint32_t b0, uint32_t b1) {
    asm volatile("mma.sync.aligned.m16n8k16.row.col.f32.bf16.bf16.f32 "
                 "{%0,%1,%2,%3}, {%4,%5,%6,%7}, {%8,%9}, {%0,%1,%2,%3};"
                 : "+f"(c[0]), "+f"(c[1]), "+f"(c[2]), "+f"(c[3])
                 : "r"(a[0]), "r"(a[1]), "r"(a[2]), "r"(a[3]), "r"(b0), "r"(b1));
}

// ---------------- zero kernels ----------------
__global__ void zero_stats_kernel() {
    int i = threadIdx.x;            // 256 threads, 1 block
    ((double2*)g_stats0)[i] = make_double2(0.0, 0.0);
    ((double2*)g_stats1)[i] = make_double2(0.0, 0.0);
}

// WHICH==0: zero g_t0 batch slice (FFd*32 float4); WHICH==1: g_t1 slice (NN*32)
template <int WHICH>
__global__ void zero_slice_kernel(int batch) {
    int i = blockIdx.x * blockDim.x + threadIdx.x;
    int n4 = (WHICH == 0) ? FFd * 32 : NN * 32;
    if (i >= n4) return;
    float4* p = (WHICH == 0) ? ((float4*)g_t0 + (size_t)batch * (FFd * 32))
                             : ((float4*)g_t1 + (size_t)batch * (NN * 32));
    p[i] = make_float4(0.f, 0.f, 0.f, 0.f);
}

// ---------------- fused elu + column stats -----------------------------------------
// WHICH==0: v -> g_xin, accumulate cols [0..127] of stats1
// WHICH==1: f -> g_fin, accumulate cols [0..127] of stats0
// Thread's column-quad is fixed: cq = tid & 31 (since grid stride % 32 == 0).
template <int WHICH>
__global__ void elu_stats_kernel(const float4* __restrict__ in, int n4) {
    __shared__ float rs[8][32][4], rq[8][32][4];
    float4* out   = (float4*)(WHICH == 0 ? g_xin : g_fin);
    double* stats = (WHICH == 0) ? g_stats1 : g_stats0;
    int tid = threadIdx.x;
    float s[4] = {0.f, 0.f, 0.f, 0.f}, q2[4] = {0.f, 0.f, 0.f, 0.f};
    for (int i = blockIdx.x * blockDim.x + tid; i < n4; i += gridDim.x * blockDim.x) {
        float4 v = in[i];
        v.x = elu1(v.x); v.y = elu1(v.y); v.z = elu1(v.z); v.w = elu1(v.w);
        out[i] = v;
        s[0] += v.x; q2[0] += v.x * v.x;
        s[1] += v.y; q2[1] += v.y * v.y;
        s[2] += v.z; q2[2] += v.z * v.z;
        s[3] += v.w; q2[3] += v.w * v.w;
    }
    int cq = tid & 31, rt = tid >> 5;
#pragma unroll
    for (int e = 0; e < 4; e++) { rs[rt][cq][e] = s[e]; rq[rt][cq][e] = q2[e]; }
    __syncthreads();
    if (tid < 128) {
        int e = tid & 3, c = tid >> 2;
        float t = 0.f;
#pragma unroll
        for (int r = 0; r < 8; r++) t += rs[r][c][e];
        atomicAdd(&stats[c * 4 + e], (double)t);
    } else {
        int t2 = tid - 128;
        int e = t2 & 3, c = t2 >> 2;
        float t = 0.f;
#pragma unroll
        for (int r = 0; r < 8; r++) t += rq[r][c][e];
        atomicAdd(&stats[256 + c * 4 + e], (double)t);
    }
}

// ---- second-half stats over t0 / t1 (concat columns 128..255) ----
template <int PASS>
__global__ void halfstats_kernel(int n4) {
    __shared__ float rs[8][32][4], rq[8][32][4];
    const float4* src = (PASS == 0) ? (const float4*)g_t0 : (const float4*)g_t1;
    double* stats     = (PASS == 0) ? g_stats0 : g_stats1;
    int tid = threadIdx.x;
    float s[4] = {0.f, 0.f, 0.f, 0.f}, q2[4] = {0.f, 0.f, 0.f, 0.f};
    for (int i = blockIdx.x * blockDim.x + tid; i < n4; i += gridDim.x * blockDim.x) {
        float4 v = src[i];
        s[0] += v.x; q2[0] += v.x * v.x;
        s[1] += v.y; q2[1] += v.y * v.y;
        s[2] += v.z; q2[2] += v.z * v.z;
        s[3] += v.w; q2[3] += v.w * v.w;
    }
    int cq = tid & 31, rt = tid >> 5;
#pragma unroll
    for (int e = 0; e < 4; e++) { rs[rt][cq][e] = s[e]; rq[rt][cq][e] = q2[e]; }
    __syncthreads();
    if (tid < 128) {
        int e = tid & 3, c = tid >> 2;
        float t = 0.f;
#pragma unroll
        for (int r = 0; r < 8; r++) t += rs[r][c][e];
        atomicAdd(&stats[128 + c * 4 + e], (double)t);
    } else {
        int t2 = tid - 128;
        int e = t2 & 3, c = t2 >> 2;
        float t = 0.f;
#pragma unroll
        for (int r = 0; r < 8; r++) t += rq[r][c][e];
        atomicAdd(&stats[384 + c * 4 + e], (double)t);
    }
}

// ---------------- sparse COO spmm, one batch per launch (L2-resident dst) ----------
// Warp handles 4 edges; lane = (e_sub)*8 + q. PASS0: xin -> t0;  PASS1: g_g -> t1.
template <int PASS>
__global__ void spbmm_kernel(const int* __restrict__ rows, const int* __restrict__ cols,
                             const float* __restrict__ vals, int batch) {
    int gw   = (blockIdx.x * blockDim.x + threadIdx.x) >> 5;
    int lane = threadIdx.x & 31;
    int e    = gw * 4 + (lane >> 3);
    int q    = lane & 7;
    if (e >= NNZk) return;
    int   r = rows[e];
    int   c = cols[e];
    float v = vals[e];
    const float* src = (PASS == 0) ? (g_xin + (size_t)batch * NN * 128)
                                   : (g_g   + (size_t)batch * FFd * 128);
    float*       dst = (PASS == 0) ? (g_t0 + (size_t)batch * FFd * 128)
                                   : (g_t1 + (size_t)batch * NN * 128);
    float4 x = *(const float4*)(src + (size_t)c * 32 + q * 4);
    x.x *= v; x.y *= v; x.z *= v; x.w *= v;
    asm volatile("red.global.add.v4.f32 [%0], {%1, %2, %3, %4};"
                 :: "l"(dst + (size_t)r * 32 + q * 4), "f"(x.x), "f"(x.y), "f"(x.z), "f"(x.w)
                 : "memory");
}

// ---- finalize BN + fold into linear; emit bf16 hi/lo weights + fused bias ----
template <int PASS>
__global__ void finalize_fold_kernel(const float* __restrict__ gamma, const float* __restrict__ beta,
                                     const float* __restrict__ w, const float* __restrict__ bias,
                                     int M) {
    __shared__ float a_s[256], sh_s[256];
    const double* stats = (PASS == 0) ? g_stats0 : g_stats1;
    __nv_bfloat16* whi = (PASS == 0) ? g_w0hi : g_w1hi;
    __nv_bfloat16* wlo = (PASS == 0) ? g_w0lo : g_w1lo;
    float* bp = (PASS == 0) ? g_b0p : g_b1p;
    int j = threadIdx.x;
    double invM = 1.0 / (double)M;
    double mu   = stats[j] * invM;
    double var  = stats[256 + j] * invM - mu * mu;
    float a  = gamma[j] * rsqrtf((float)var + 1e-5f);
    float sh = beta[j] - (float)mu * a;
    a_s[j] = a; sh_s[j] = sh;
    __syncthreads();
    for (int idx = j; idx < 128 * 256; idx += 256) {
        float wv = w[idx] * a_s[idx & 255];
        __nv_bfloat16 hi = __float2bfloat16(wv);
        __nv_bfloat16 lo = __float2bfloat16(wv - __bfloat162float(hi));
        whi[idx] = hi; wlo[idx] = lo;
    }
    if (j < 128) {
        float s = bias[j];
        const float* wr = w + j * 256;
        for (int q = 0; q < 256; q++) s += sh_s[q] * wr[q];
        bp[j] = s;
    }
}

// ---------------- HMMA bf16 GEMM: out[M,128] = [A0|A1][M,256] @ Wp[128,256]^T + bp ----
// 3-term compensation: D = Ahi*Whi + Ahi*Wlo + Alo*Whi.
// CTA tile 128x128, 8 warps = 4(M) x 2(N), warp m32 x n64 via mma.m16n8k16.
#define OF_BIAS 0
#define OF_AHI  1024
#define OF_ALO  (1024 + 16384)
#define OF_WHI  (1024 + 32768)
#define OF_WLO  (1024 + 49152)
#define SMEM_SZ (1024 + 65536)

template <int PASS>
__global__ void __launch_bounds__(256, 2)
gemm_mma_kernel(const float* __restrict__ resid, float* __restrict__ out, int M) {
    extern __shared__ char smem[];
    const float* A0 = (PASS == 0) ? g_fin : g_xin;
    const float* A1 = (PASS == 0) ? g_t0  : g_t1;
    const __nv_bfloat16* Whi = (PASS == 0) ? g_w0hi : g_w1hi;
    const __nv_bfloat16* Wlo = (PASS == 0) ? g_w0lo : g_w1lo;
    const float* bp = (PASS == 0) ? g_b0p : g_b1p;

    uint32_t sb = smem_u32(smem);
    int tid  = threadIdx.x;
    int wid  = tid >> 5;
    int lane = tid & 31;
    int m0   = blockIdx.x * 128;
    int wm   = (wid & 3) * 32;
    int wn   = (wid >> 2) * 64;

    if (tid < 128) *(float*)(smem + OF_BIAS + tid * 4) = bp[tid];

    float acc[2][8][4];
#pragma unroll
    for (int mt = 0; mt < 2; mt++)
#pragma unroll
        for (int nt = 0; nt < 8; nt++)
#pragma unroll
            for (int e = 0; e < 4; e++) acc[mt][nt][e] = 0.f;

    int lrow = (lane & 7) + ((lane >> 3) & 1) * 8;
    int lkg  = lane >> 4;

    for (int ch = 0; ch < 4; ch++) {
        const float* Asrc = (ch < 2) ? A0 : A1;
        int kbA = (ch & 1) * 64;
        int kgW = ch * 8;
        if (ch) __syncthreads();

#pragma unroll
        for (int i = 0; i < 4; i++) {
            int idx = tid + i * 256;
            int row = idx >> 3;
            int u   = idx & 7;
            float af[8];
            if (m0 + row < M) {
                const float* ap = Asrc + (size_t)(m0 + row) * 128 + kbA + u * 8;
                float4 a0 = *(const float4*)ap;
                float4 a1 = *(const float4*)(ap + 4);
                af[0]=a0.x; af[1]=a0.y; af[2]=a0.z; af[3]=a0.w;
                af[4]=a1.x; af[5]=a1.y; af[6]=a1.z; af[7]=a1.w;
            } else {
#pragma unroll
                for (int e = 0; e < 8; e++) af[e] = 0.f;
            }
            __nv_bfloat16 hi[8], lo[8];
#pragma unroll
            for (int e = 0; e < 8; e++) {
                hi[e] = __float2bfloat16(af[e]);
                lo[e] = __float2bfloat16(af[e] - __bfloat162float(hi[e]));
            }
            uint32_t off = SW128((uint32_t)(row * 128 + u * 16));
            *(uint4*)(smem + OF_AHI + off) = *(const uint4*)hi;
            *(uint4*)(smem + OF_ALO + off) = *(const uint4*)lo;
        }
#pragma unroll
        for (int i = 0; i < 4; i++) {
            int idx = tid + i * 256;
            int row = idx >> 3;
            int u   = idx & 7;
            uint32_t off = SW128((uint32_t)(row * 128 + u * 16));
            *(uint4*)(smem + OF_WHI + off) = ((const uint4*)Whi)[row * 32 + kgW + u];
            *(uint4*)(smem + OF_WLO + off) = ((const uint4*)Wlo)[row * 32 + kgW + u];
        }
        __syncthreads();

#pragma unroll
        for (int ks = 0; ks < 4; ks++) {
            uint32_t ahi[2][4], alo[2][4];
#pragma unroll
            for (int mt = 0; mt < 2; mt++) {
                uint32_t aoff = SW128((uint32_t)((wm + mt * 16 + lrow) * 128 + (ks * 2 + lkg) * 16));
                ldsm4(ahi[mt], sb + OF_AHI + aoff);
                ldsm4(alo[mt], sb + OF_ALO + aoff);
            }
#pragma unroll
            for (int nt2 = 0; nt2 < 4; nt2++) {
                uint32_t boff = SW128((uint32_t)((wn + nt2 * 16 + lrow) * 128 + (ks * 2 + lkg) * 16));
                uint32_t bh[4], bl[4];
                ldsm4(bh, sb + OF_WHI + boff);
                ldsm4(bl, sb + OF_WLO + boff);
#pragma unroll
                for (int mt = 0; mt < 2; mt++) {
                    mma16816(acc[mt][nt2 * 2 + 0], ahi[mt], bh[0], bh[2]);
                    mma16816(acc[mt][nt2 * 2 + 1], ahi[mt], bh[1], bh[3]);
                    mma16816(acc[mt][nt2 * 2 + 0], ahi[mt], bl[0], bl[2]);
                    mma16816(acc[mt][nt2 * 2 + 1], ahi[mt], bl[1], bl[3]);
                    mma16816(acc[mt][nt2 * 2 + 0], alo[mt], bh[0], bh[2]);
                    mma16816(acc[mt][nt2 * 2 + 1], alo[mt], bh[1], bh[3]);
                }
            }
        }
    }

    const float* bias_s = (const float*)(smem + OF_BIAS);
    int r0 = lane >> 2;
    int cp = (lane & 3) * 2;
#pragma unroll
    for (int mt = 0; mt < 2; mt++) {
#pragma unroll
        for (int nt = 0; nt < 8; nt++) {
            int col = wn + nt * 8 + cp;
            float b0 = bias_s[col], b1 = bias_s[col + 1];
#pragma unroll
            for (int h = 0; h < 2; h++) {
                int rr = m0 + wm + mt * 16 + r0 + h * 8;
                if (rr >= M) continue;
                size_t base = (size_t)rr * 128 + col;
                float v0 = acc[mt][nt][h * 2 + 0] + b0;
                float v1 = acc[mt][nt][h * 2 + 1] + b1;
                if (PASS == 1) {
                    float2 rd = *(const float2*)(resid + base);
                    v0 += rd.x; v1 += rd.y;
                }
                *(float2*)(out + base) = make_float2(v0, v1);
                if (PASS == 0)
                    *(float2*)(g_g + base) = make_float2(elu1(v0), elu1(v1));
            }
        }
    }
}

// ---------------- launch ----------------
extern "C" void kernel_launch(void* const* d_in, const int* in_sizes, int n_in,
                              void* d_out, int out_size) {
    const int*   Di_rows  = (const int*)d_in[0];
    const int*   Di_cols  = (const int*)d_in[1];
    const float* Di_vals  = (const float*)d_in[2];
    const int*   DiA_rows = (const int*)d_in[3];
    const int*   DiA_cols = (const int*)d_in[4];
    const float* DiA_vals = (const float*)d_in[5];
    const float* v_in     = (const float*)d_in[6];
    const float* f_in     = (const float*)d_in[7];
    const float* bn0_g    = (const float*)d_in[8];
    const float* bn0_b    = (const float*)d_in[9];
    const float* fc0_w    = (const float*)d_in[10];
    const float* fc0_b    = (const float*)d_in[11];
    const float* bn1_g    = (const float*)d_in[12];
    const float* bn1_b    = (const float*)d_in[13];
    const float* fc1_w    = (const float*)d_in[14];
    const float* fc1_b    = (const float*)d_in[15];

    float* out_v = (float*)d_out;                 // v + v_out : [4,30000,128]
    float* out_f = out_v + SZ_V;                  // f_out     : [4,60000,128]

    const int T = 256;
    const int nv4 = (int)(SZ_V / 4);
    const int nf4 = (int)(SZ_F / 4);
    const int spGrid = (NNZk / 4 * 32) / T;       // 22500 blocks

    cudaFuncSetAttribute(gemm_mma_kernel<0>, cudaFuncAttributeMaxDynamicSharedMemorySize, SMEM_SZ);
    cudaFuncSetAttribute(gemm_mma_kernel<1>, cudaFuncAttributeMaxDynamicSharedMemorySize, SMEM_SZ);

    // 0) zero stats
    zero_stats_kernel<<<1, 256>>>();

    // 1) elu inputs + first-half BN stats
    elu_stats_kernel<0><<<1024, T>>>((const float4*)v_in, nv4);
    elu_stats_kernel<1><<<1024, T>>>((const float4*)f_in, nf4);

    // 2) spbmm1 per batch: zero slice (L2-warm) then scatter
    for (int b = 0; b < BB; b++) {
        zero_slice_kernel<0><<<(FFd * 32 + T - 1) / T, T>>>(b);
        spbmm_kernel<0><<<spGrid, T>>>(Di_rows, Di_cols, Di_vals, b);
    }

    // 3) BN0 second-half stats + fold into fc0
    halfstats_kernel<0><<<1024, T>>>(nf4);
    finalize_fold_kernel<0><<<1, 256>>>(bn0_g, bn0_b, fc0_w, fc0_b, BB * FFd);

    // 4) gemm0: f_out (+ elu copy into g_g)
    gemm_mma_kernel<0><<<(BB * FFd + 127) / 128, 256, SMEM_SZ>>>(nullptr, out_f, BB * FFd);

    // 5) spbmm2 per batch
    for (int b = 0; b < BB; b++) {
        zero_slice_kernel<1><<<(NN * 32 + T - 1) / T, T>>>(b);
        spbmm_kernel<1><<<spGrid, T>>>(DiA_rows, DiA_cols, DiA_vals, b);
    }

    // 6) BN1 second-half stats + fold into fc1
    halfstats_kernel<1><<<1024, T>>>(nv4);
    finalize_fold_kernel<1><<<1, 256>>>(bn1_g, bn1_b, fc1_w, fc1_b, BB * NN);

    // 7) gemm1: out_v = v + linear(...)
    gemm_mma_kernel<1><<<(BB * NN + 127) / 128, 256, SMEM_SZ>>>(v_in, out_v, BB * NN);
}